// round 15
// baseline (speedup 1.0000x reference)
#include <cuda_runtime.h>

#define BB 128
#define MM 60
#define FG 19
#define NCc 80
#define CELLS (FG*FG)      // 361
#define NBLK (BB*3)        // 384
#define NTHR 384
#define NWRP 12

__device__ double g_acc[6];
__device__ int    g_done;

// anchors / 32 (exact in fp32) and reciprocals
__constant__ float c_aw[9] = {0.3125f, 0.5f,     1.03125f, 0.9375f, 1.9375f,
                              1.84375f, 3.625f,  4.875f,   11.65625f};
__constant__ float c_ah[9] = {0.40625f, 0.9375f, 0.71875f, 1.90625f, 1.40625f,
                              3.71875f, 2.8125f, 6.1875f,  10.1875f};
__constant__ float c_iaw[3] = {1.0f/3.625f, 1.0f/4.875f, 1.0f/11.65625f};
__constant__ float c_iah[3] = {1.0f/2.8125f, 1.0f/6.1875f, 1.0f/10.1875f};

__device__ __forceinline__ float sigm(float z) { return 1.f / (1.f + __expf(-z)); }

// One block per (batch, anchor). 384 threads, 4 blocks/SM. R14 structure;
// IoU loop fully unrolled with 6 independent max-chains (bitwise-identical
// result: max is associative/commutative).
__global__ void __launch_bounds__(NTHR, 4)
k_fused(const float* __restrict__ out, const float* __restrict__ labels,
        float* __restrict__ o) {
    int b = blockIdx.x;
    int anc = blockIdx.y;
    int tid = threadIdx.x;
    int wid = tid >> 5, lane = tid & 31;

    __shared__ float4 sTc[MM];        // truth corners x1,y1,x2,y2
    __shared__ float  sTb[MM];        // truth area (bA)
    __shared__ float  sPayT[MM][3];   // tw, th, l4 (raw)
    __shared__ int    sCellI[CELLS];  // winning label per cell (atomicMax), -1
    __shared__ short  sMm[MM];
    __shared__ short  sMloc[MM];
    __shared__ int    sN;
    __shared__ float  sRed[NWRP][5];

    // ---- label loads first (scatter latency chain starts immediately) ----
    float l0 = 0.f, l1 = 0.f, l2 = 0.f, l3 = 0.f, l4 = 0.f;
    if (tid < MM) {
        const float* L = labels + (size_t)(b * MM + tid) * 5;
        l0 = __ldg(L); l1 = __ldg(L+1); l2 = __ldg(L+2); l3 = __ldg(L+3); l4 = __ldg(L+4);
    }

    // ---- prefetch this cell's 5 channel values ----
    float x0 = 0.f, y0 = 0.f, zw = 0.f, zh = 0.f, zo = 0.f;
    size_t base = ((size_t)(b * 255 + anc * 85)) * CELLS;
    if (tid < CELLS) {
        x0 = __ldg(&out[base + tid]);
        y0 = __ldg(&out[base + tid + CELLS]);
        zw = __ldg(&out[base + tid + 2 * CELLS]);
        zh = __ldg(&out[base + tid + 3 * CELLS]);
        zo = __ldg(&out[base + tid + 4 * CELLS]);
    }

    if (tid == 0) sN = 0;
    for (int t = tid; t < CELLS; t += NTHR) sCellI[t] = -1;

    // ---- per-label truth boxes + anchor matching + atomicMax claim ----
    int myflat = -1;
    if (tid < MM) {
        int m = tid;
        bool valid = (l0 + l1 + l2 + l3 + l4) > 0.0f;
        float tx = floorf(l0 * 0.03125f);
        float ty = floorf(l1 * 0.03125f);
        float tw = floorf((l2 - l0) * 0.03125f);
        float th = floorf((l3 - l1) * 0.03125f);
        float ta = tw * th;

        if (valid) {
            float hw = tw * 0.5f, hh = th * 0.5f;
            sTc[m] = make_float4(tx - hw, ty - hh, tx + hw, ty + hh);
            sTb[m] = ta;
        } else {
            sTc[m] = make_float4(3e18f, 3e18f, 3e18f, 3e18f);
            sTb[m] = 0.f;
        }

        float best = -1.0f; int bi = 0;
        #pragma unroll
        for (int k = 0; k < 9; k++) {
            float mw = fminf(tw, c_aw[k]);
            float mh = fminf(th, c_ah[k]);
            float inter = (mw > 0.f && mh > 0.f) ? mw * mh : 0.f;
            float aiou = __fdividef(inter, ta + c_aw[k] * c_ah[k] - inter);
            if (aiou > best) { best = aiou; bi = k; }
        }

        if (valid && bi == 6 + anc) {
            int ti = (int)tx, tj = (int)ty;
            if (ti >= 0 && ti < FG && tj >= 0 && tj < FG) {
                myflat = tj * FG + ti;
                sPayT[m][0] = tw; sPayT[m][1] = th; sPayT[m][2] = l4;
                atomicMax(&sCellI[myflat], m);   // last-label-wins == max m
            }
        }
    }
    __syncthreads();

    // winners append to the matched list
    if (tid < MM && myflat >= 0 && sCellI[myflat] == tid) {
        int p = atomicAdd(&sN, 1);
        sMm[p] = (short)tid;
        sMloc[p] = (short)myflat;
    }
    __syncthreads();

    // ---- class + matched-loss prefetch (LDGs issued before the IoU loop) ----
    int n = sN;
    float cz0[2], cz1[2], cz2[2], mx0[2], my0[2], mzw[2], mzh[2], mzo[2];
    int ment[2];
    #pragma unroll
    for (int q = 0; q < 2; q++) {
        int e = wid + q * NWRP;
        ment[q] = (e < n) ? e : -1;
        cz0[q] = cz1[q] = cz2[q] = 0.f;
        mx0[q] = my0[q] = mzw[q] = mzh[q] = mzo[q] = 0.f;
        if (ment[q] >= 0) {
            int idx = sMloc[e];
            size_t cb = base + idx;
            cz0[q] = __ldg(&out[cb + (size_t)(5 + lane) * CELLS]);
            cz1[q] = __ldg(&out[cb + (size_t)(37 + lane) * CELLS]);
            if (lane < 16) cz2[q] = __ldg(&out[cb + (size_t)(69 + lane) * CELLS]);
            if (lane == 0) {
                mx0[q] = __ldg(&out[cb]);
                my0[q] = __ldg(&out[cb + CELLS]);
                mzw[q] = __ldg(&out[cb + 2 * CELLS]);
                mzh[q] = __ldg(&out[cb + 3 * CELLS]);
                mzo[q] = __ldg(&out[cb + 4 * CELLS]);
            }
        }
    }

    // ---- per-cell channel math (7 MUFU) + IoU + UNMATCHED obj loss ----
    float a_xy = 0.f, a_wh = 0.f, a_obj = 0.f, a_cls = 0.f, a_l2 = 0.f;

    if (tid < CELLS) {
        int j = tid / FG, i = tid - j * FG;

        float ex = __expf(-x0);               // EX2
        float ey = __expf(-y0);               // EX2
        float eo = __expf(-zo);               // EX2
        float dx = 1.f + ex, dy = 1.f + ey, dz = 1.f + eo;
        float dxy = dx * dy;
        float r = __fdividef(1.f, dxy * dz);  // ONE RCP for all three sigmoids
        float sx = dy * dz * r;
        float sy = dx * dz * r;
        float so = dxy * r;

        float pw = __expf(zw) * c_aw[6 + anc];  // EX2
        float ph = __expf(zh) * c_ah[6 + anc];  // EX2
        float px = sx + (float)i;
        float py = sy + (float)j;
        float ax1 = px - 0.5f * pw, ax2 = px + 0.5f * pw;
        float ay1 = py - 0.5f * ph, ay2 = py + 0.5f * ph;
        float pA = pw * ph;

        // fully unrolled, 6 independent max-chains (60 = 6 x 10)
        float d0 = -1e30f, d1 = -1e30f, d2 = -1e30f,
              d3 = -1e30f, d4 = -1e30f, d5 = -1e30f;
        #pragma unroll
        for (int m = 0; m < MM; m += 6) {
            {
                float4 c = sTc[m];   float bA = sTb[m];
                float w = fminf(ax2, c.z) - fmaxf(ax1, c.x);
                float h = fminf(ay2, c.w) - fmaxf(ay1, c.y);
                float inter = fmaxf(w, 0.f) * h;
                d0 = fmaxf(d0, __fmaf_rn(inter, 3.f, -bA));
            }
            {
                float4 c = sTc[m+1]; float bA = sTb[m+1];
                float w = fminf(ax2, c.z) - fmaxf(ax1, c.x);
                float h = fminf(ay2, c.w) - fmaxf(ay1, c.y);
                float inter = fmaxf(w, 0.f) * h;
                d1 = fmaxf(d1, __fmaf_rn(inter, 3.f, -bA));
            }
            {
                float4 c = sTc[m+2]; float bA = sTb[m+2];
                float w = fminf(ax2, c.z) - fmaxf(ax1, c.x);
                float h = fminf(ay2, c.w) - fmaxf(ay1, c.y);
                float inter = fmaxf(w, 0.f) * h;
                d2 = fmaxf(d2, __fmaf_rn(inter, 3.f, -bA));
            }
            {
                float4 c = sTc[m+3]; float bA = sTb[m+3];
                float w = fminf(ax2, c.z) - fmaxf(ax1, c.x);
                float h = fminf(ay2, c.w) - fmaxf(ay1, c.y);
                float inter = fmaxf(w, 0.f) * h;
                d3 = fmaxf(d3, __fmaf_rn(inter, 3.f, -bA));
            }
            {
                float4 c = sTc[m+4]; float bA = sTb[m+4];
                float w = fminf(ax2, c.z) - fmaxf(ax1, c.x);
                float h = fminf(ay2, c.w) - fmaxf(ay1, c.y);
                float inter = fmaxf(w, 0.f) * h;
                d4 = fmaxf(d4, __fmaf_rn(inter, 3.f, -bA));
            }
            {
                float4 c = sTc[m+5]; float bA = sTb[m+5];
                float w = fminf(ax2, c.z) - fmaxf(ax1, c.x);
                float h = fminf(ay2, c.w) - fmaxf(ay1, c.y);
                float inter = fmaxf(w, 0.f) * h;
                d5 = fmaxf(d5, __fmaf_rn(inter, 3.f, -bA));
            }
        }
        float dd = fmaxf(fmaxf(fmaxf(d0, d1), fmaxf(d2, d3)), fmaxf(d4, d5));

        // log(1-so) = -zo - log(dz)  (one LG2, no cancellation)
        bool take = (sCellI[tid] < 0) && (dd <= pA);
        float lqo = fmaxf(-zo - __logf(dz), -100.f);   // LG2
        a_obj = take ? -lqo : 0.f;
        a_l2  = take ? so * so : 0.f;
    }

    // ---- matched entries: class BCE on lanes, box/obj losses on lane 0 ----
    #pragma unroll
    for (int q = 0; q < 2; q++) {
        if (ment[q] >= 0) {
            int e = ment[q];
            int m = sMm[e];
            int cls = (int)sPayT[m][2];
            {
                float p = sigm(cz0[q]);
                float lp = fmaxf(__logf(p), -100.f);
                float lq = fmaxf(__logf(1.f - p), -100.f);
                float t = (lane == cls) ? 1.f : 0.f;
                a_cls += -(t * lp + (1.f - t) * lq);
                float ee = p - t; a_l2 += ee * ee;
            }
            {
                float p = sigm(cz1[q]);
                float lp = fmaxf(__logf(p), -100.f);
                float lq = fmaxf(__logf(1.f - p), -100.f);
                float t = (lane + 32 == cls) ? 1.f : 0.f;
                a_cls += -(t * lp + (1.f - t) * lq);
                float ee = p - t; a_l2 += ee * ee;
            }
            if (lane < 16) {
                float p = sigm(cz2[q]);
                float lp = fmaxf(__logf(p), -100.f);
                float lq = fmaxf(__logf(1.f - p), -100.f);
                float t = (lane + 64 == cls) ? 1.f : 0.f;
                a_cls += -(t * lp + (1.f - t) * lq);
                float ee = p - t; a_l2 += ee * ee;
            }
            if (lane == 0) {
                // txf = tyf = 0 exactly
                float tw = sPayT[m][0], th = sPayT[m][1];
                float ta = sTb[m];
                float msx = sigm(mx0[q]), msy = sigm(my0[q]), mso = sigm(mzo[q]);
                float twt = __logf(__fmaf_rn(tw, c_iaw[anc], 1e-16f));
                float tht = __logf(__fmaf_rn(th, c_iah[anc], 1e-16f));
                float w2 = 2.0f - ta * (1.0f / 361.0f);
                float lqx = fmaxf(__logf(1.f - msx), -100.f);
                float lqy = fmaxf(__logf(1.f - msy), -100.f);
                a_xy += -w2 * (lqx + lqy);
                float dw = mzw[q] - twt, dh = mzh[q] - tht;
                float whs = w2 * (dw * dw + dh * dh);
                a_wh += 0.5f * whs;
                a_obj += -fmaxf(__logf(mso), -100.f);
                float eo2 = mso - 1.f;
                a_l2 += msx * msx + msy * msy + whs + eo2 * eo2;
            }
        }
    }

    // ---- leftover matched entries (n > 24), rare ----
    for (int e = 2 * NWRP + wid; e < n; e += NWRP) {
        int m = sMm[e];
        int idx = sMloc[e];
        int cls = (int)sPayT[m][2];
        size_t cb = base + idx;
        #pragma unroll
        for (int r2 = 0; r2 < 3; r2++) {
            int cc = lane + r2 * 32;
            if (cc < NCc) {
                float z = __ldg(&out[cb + (size_t)(5 + cc) * CELLS]);
                float p = sigm(z);
                float lp = fmaxf(__logf(p), -100.f);
                float lq = fmaxf(__logf(1.f - p), -100.f);
                float t = (cc == cls) ? 1.f : 0.f;
                a_cls += -(t * lp + (1.f - t) * lq);
                float ee = p - t; a_l2 += ee * ee;
            }
        }
        if (lane == 0) {
            float tw = sPayT[m][0], th = sPayT[m][1];
            float ta = sTb[m];
            float msx = sigm(__ldg(&out[cb]));
            float msy = sigm(__ldg(&out[cb + CELLS]));
            float lzw = __ldg(&out[cb + 2 * CELLS]);
            float lzh = __ldg(&out[cb + 3 * CELLS]);
            float mso = sigm(__ldg(&out[cb + 4 * CELLS]));
            float twt = __logf(__fmaf_rn(tw, c_iaw[anc], 1e-16f));
            float tht = __logf(__fmaf_rn(th, c_iah[anc], 1e-16f));
            float w2 = 2.0f - ta * (1.0f / 361.0f);
            float lqx = fmaxf(__logf(1.f - msx), -100.f);
            float lqy = fmaxf(__logf(1.f - msy), -100.f);
            a_xy += -w2 * (lqx + lqy);
            float dw = lzw - twt, dh = lzh - tht;
            float whs = w2 * (dw * dw + dh * dh);
            a_wh += 0.5f * whs;
            a_obj += -fmaxf(__logf(mso), -100.f);
            float eo2 = mso - 1.f;
            a_l2 += msx * msx + msy * msy + whs + eo2 * eo2;
        }
    }

    // ---- reduce ----
    unsigned msk = 0xffffffffu;
    for (int off = 16; off > 0; off >>= 1) {
        a_xy  += __shfl_down_sync(msk, a_xy, off);
        a_wh  += __shfl_down_sync(msk, a_wh, off);
        a_obj += __shfl_down_sync(msk, a_obj, off);
        a_cls += __shfl_down_sync(msk, a_cls, off);
        a_l2  += __shfl_down_sync(msk, a_l2, off);
    }
    if (lane == 0) {
        sRed[wid][0] = a_xy; sRed[wid][1] = a_wh; sRed[wid][2] = a_obj;
        sRed[wid][3] = a_cls; sRed[wid][4] = a_l2;
    }
    __syncthreads();
    if (tid == 0) {
        float r0 = 0.f, r1 = 0.f, r2 = 0.f, r3 = 0.f, r4 = 0.f;
        #pragma unroll
        for (int w = 0; w < NWRP; w++) {
            r0 += sRed[w][0]; r1 += sRed[w][1]; r2 += sRed[w][2];
            r3 += sRed[w][3]; r4 += sRed[w][4];
        }
        atomicAdd(&g_acc[1], (double)r0);
        atomicAdd(&g_acc[2], (double)r1);
        atomicAdd(&g_acc[3], (double)r2);
        atomicAdd(&g_acc[4], (double)r3);
        atomicAdd(&g_acc[5], (double)r4);
        __threadfence();
        int d = atomicAdd(&g_done, 1);
        if (d == NBLK - 1) {
            double xy = atomicAdd(&g_acc[1], 0.0);
            double wh = atomicAdd(&g_acc[2], 0.0);
            double ob = atomicAdd(&g_acc[3], 0.0);
            double cl = atomicAdd(&g_acc[4], 0.0);
            double l2 = atomicAdd(&g_acc[5], 0.0);
            o[0] = (float)(xy + wh + ob + cl);
            o[1] = (float)xy;
            o[2] = (float)wh;
            o[3] = (float)ob;
            o[4] = (float)cl;
            o[5] = (float)l2;
            g_acc[1] = 0.0; g_acc[2] = 0.0; g_acc[3] = 0.0;
            g_acc[4] = 0.0; g_acc[5] = 0.0;
            g_done = 0;
        }
    }
}

extern "C" void kernel_launch(void* const* d_in, const int* in_sizes, int n_in,
                              void* d_out, int out_size) {
    const float* output = (const float*)d_in[0];
    const float* labels = (const float*)d_in[1];
    float* o = (float*)d_out;
    (void)in_sizes; (void)n_in; (void)out_size;

    dim3 grid(BB, 3);
    k_fused<<<grid, NTHR>>>(output, labels, o);
}

// round 16
// speedup vs baseline: 1.0928x; 1.0928x over previous
#include <cuda_runtime.h>

#define BB 128
#define MM 60
#define FG 19
#define NCc 80
#define CELLS (FG*FG)      // 361
#define NBLK (BB*3)        // 384
#define NTHR 384
#define NWRP 12

__device__ double g_acc[6];
__device__ int    g_done;

// anchors / 32 (exact in fp32) and reciprocals
__constant__ float c_aw[9] = {0.3125f, 0.5f,     1.03125f, 0.9375f, 1.9375f,
                              1.84375f, 3.625f,  4.875f,   11.65625f};
__constant__ float c_ah[9] = {0.40625f, 0.9375f, 0.71875f, 1.90625f, 1.40625f,
                              3.71875f, 2.8125f, 6.1875f,  10.1875f};
__constant__ float c_iaw[3] = {1.0f/3.625f, 1.0f/4.875f, 1.0f/11.65625f};
__constant__ float c_iah[3] = {1.0f/2.8125f, 1.0f/6.1875f, 1.0f/10.1875f};

__device__ __forceinline__ float sigm(float z) { return 1.f / (1.f + __expf(-z)); }

// One block per (batch, anchor). 384 threads, 4 blocks/SM. R9 structure
// (two barriers); per-cell transcendental path reworked to 7 MUFU ops.
__global__ void __launch_bounds__(NTHR, 4)
k_fused(const float* __restrict__ out, const float* __restrict__ labels,
        float* __restrict__ o) {
    int b = blockIdx.x;
    int anc = blockIdx.y;
    int tid = threadIdx.x;
    int wid = tid >> 5, lane = tid & 31;

    __shared__ float4 sTc[MM];        // truth corners x1,y1,x2,y2
    __shared__ float  sTb[MM];        // truth area (bA)
    __shared__ float  sPayT[MM][3];   // tw, th, l4 (raw)
    __shared__ int    sCellI[CELLS];  // winning label per cell (atomicMax), -1
    __shared__ short  sMm[MM];
    __shared__ short  sMloc[MM];
    __shared__ int    sN;
    __shared__ float  sRed[NWRP][5];

    // ---- label loads first (scatter latency chain starts immediately) ----
    float l0 = 0.f, l1 = 0.f, l2 = 0.f, l3 = 0.f, l4 = 0.f;
    if (tid < MM) {
        const float* L = labels + (size_t)(b * MM + tid) * 5;
        l0 = __ldg(L); l1 = __ldg(L+1); l2 = __ldg(L+2); l3 = __ldg(L+3); l4 = __ldg(L+4);
    }

    // ---- prefetch this cell's 5 channel values ----
    float x0 = 0.f, y0 = 0.f, zw = 0.f, zh = 0.f, zo = 0.f;
    size_t base = ((size_t)(b * 255 + anc * 85)) * CELLS;
    if (tid < CELLS) {
        x0 = __ldg(&out[base + tid]);
        y0 = __ldg(&out[base + tid + CELLS]);
        zw = __ldg(&out[base + tid + 2 * CELLS]);
        zh = __ldg(&out[base + tid + 3 * CELLS]);
        zo = __ldg(&out[base + tid + 4 * CELLS]);
    }

    if (tid == 0) sN = 0;
    for (int t = tid; t < CELLS; t += NTHR) sCellI[t] = -1;

    // ---- per-label truth boxes + anchor matching + atomicMax claim ----
    int myflat = -1;
    if (tid < MM) {
        int m = tid;
        bool valid = (l0 + l1 + l2 + l3 + l4) > 0.0f;
        float tx = floorf(l0 * 0.03125f);
        float ty = floorf(l1 * 0.03125f);
        float tw = floorf((l2 - l0) * 0.03125f);
        float th = floorf((l3 - l1) * 0.03125f);
        float ta = tw * th;

        if (valid) {
            float hw = tw * 0.5f, hh = th * 0.5f;
            sTc[m] = make_float4(tx - hw, ty - hh, tx + hw, ty + hh);
            sTb[m] = ta;
        } else {
            sTc[m] = make_float4(3e18f, 3e18f, 3e18f, 3e18f);
            sTb[m] = 0.f;
        }

        float best = -1.0f; int bi = 0;
        #pragma unroll
        for (int k = 0; k < 9; k++) {
            float mw = fminf(tw, c_aw[k]);
            float mh = fminf(th, c_ah[k]);
            float inter = (mw > 0.f && mh > 0.f) ? mw * mh : 0.f;
            float aiou = __fdividef(inter, ta + c_aw[k] * c_ah[k] - inter);
            if (aiou > best) { best = aiou; bi = k; }
        }

        if (valid && bi == 6 + anc) {
            int ti = (int)tx, tj = (int)ty;
            if (ti >= 0 && ti < FG && tj >= 0 && tj < FG) {
                myflat = tj * FG + ti;
                sPayT[m][0] = tw; sPayT[m][1] = th; sPayT[m][2] = l4;
                atomicMax(&sCellI[myflat], m);   // last-label-wins == max m
            }
        }
    }
    __syncthreads();

    // winners append to the matched list
    if (tid < MM && myflat >= 0 && sCellI[myflat] == tid) {
        int p = atomicAdd(&sN, 1);
        sMm[p] = (short)tid;
        sMloc[p] = (short)myflat;
    }
    __syncthreads();

    // ---- class + matched-loss prefetch (LDGs issued before the IoU loop) ----
    int n = sN;
    float cz0[2], cz1[2], cz2[2], mx0[2], my0[2], mzw[2], mzh[2], mzo[2];
    int ment[2];
    #pragma unroll
    for (int q = 0; q < 2; q++) {
        int e = wid + q * NWRP;
        ment[q] = (e < n) ? e : -1;
        cz0[q] = cz1[q] = cz2[q] = 0.f;
        mx0[q] = my0[q] = mzw[q] = mzh[q] = mzo[q] = 0.f;
        if (ment[q] >= 0) {
            int idx = sMloc[e];
            size_t cb = base + idx;
            cz0[q] = __ldg(&out[cb + (size_t)(5 + lane) * CELLS]);
            cz1[q] = __ldg(&out[cb + (size_t)(37 + lane) * CELLS]);
            if (lane < 16) cz2[q] = __ldg(&out[cb + (size_t)(69 + lane) * CELLS]);
            if (lane == 0) {
                mx0[q] = __ldg(&out[cb]);
                my0[q] = __ldg(&out[cb + CELLS]);
                mzw[q] = __ldg(&out[cb + 2 * CELLS]);
                mzh[q] = __ldg(&out[cb + 3 * CELLS]);
                mzo[q] = __ldg(&out[cb + 4 * CELLS]);
            }
        }
    }

    // ---- per-cell channel math (7 MUFU) + IoU + UNMATCHED obj loss ----
    float a_xy = 0.f, a_wh = 0.f, a_obj = 0.f, a_cls = 0.f, a_l2 = 0.f;

    if (tid < CELLS) {
        int j = tid / FG, i = tid - j * FG;

        float ex = __expf(-x0);               // EX2
        float ey = __expf(-y0);               // EX2
        float eo = __expf(-zo);               // EX2
        float dx = 1.f + ex, dy = 1.f + ey, dz = 1.f + eo;
        float dxy = dx * dy;
        float r = __fdividef(1.f, dxy * dz);  // ONE RCP for all three sigmoids
        float sx = dy * dz * r;
        float sy = dx * dz * r;
        float so = dxy * r;

        float pw = __expf(zw) * c_aw[6 + anc];  // EX2
        float ph = __expf(zh) * c_ah[6 + anc];  // EX2
        float px = sx + (float)i;
        float py = sy + (float)j;
        float ax1 = px - 0.5f * pw, ax2 = px + 0.5f * pw;
        float ay1 = py - 0.5f * ph, ay2 = py + 0.5f * ph;
        float pA = pw * ph;

        float d0 = -1e30f, d1 = -1e30f, d2 = -1e30f, d3 = -1e30f;
        #pragma unroll 4
        for (int m = 0; m < MM; m += 4) {
            {
                float4 c = sTc[m];   float bA = sTb[m];
                float w = fminf(ax2, c.z) - fmaxf(ax1, c.x);
                float h = fminf(ay2, c.w) - fmaxf(ay1, c.y);
                float inter = fmaxf(w, 0.f) * h;
                d0 = fmaxf(d0, __fmaf_rn(inter, 3.f, -bA));
            }
            {
                float4 c = sTc[m+1]; float bA = sTb[m+1];
                float w = fminf(ax2, c.z) - fmaxf(ax1, c.x);
                float h = fminf(ay2, c.w) - fmaxf(ay1, c.y);
                float inter = fmaxf(w, 0.f) * h;
                d1 = fmaxf(d1, __fmaf_rn(inter, 3.f, -bA));
            }
            {
                float4 c = sTc[m+2]; float bA = sTb[m+2];
                float w = fminf(ax2, c.z) - fmaxf(ax1, c.x);
                float h = fminf(ay2, c.w) - fmaxf(ay1, c.y);
                float inter = fmaxf(w, 0.f) * h;
                d2 = fmaxf(d2, __fmaf_rn(inter, 3.f, -bA));
            }
            {
                float4 c = sTc[m+3]; float bA = sTb[m+3];
                float w = fminf(ax2, c.z) - fmaxf(ax1, c.x);
                float h = fminf(ay2, c.w) - fmaxf(ay1, c.y);
                float inter = fmaxf(w, 0.f) * h;
                d3 = fmaxf(d3, __fmaf_rn(inter, 3.f, -bA));
            }
        }
        float dd = fmaxf(fmaxf(d0, d1), fmaxf(d2, d3));

        // log(1-so) = -zo - log(dz)  (one LG2, no cancellation)
        bool take = (sCellI[tid] < 0) && (dd <= pA);
        float lqo = fmaxf(-zo - __logf(dz), -100.f);   // LG2
        a_obj = take ? -lqo : 0.f;
        a_l2  = take ? so * so : 0.f;
    }

    // ---- matched entries: class BCE on lanes, box/obj losses on lane 0 ----
    #pragma unroll
    for (int q = 0; q < 2; q++) {
        if (ment[q] >= 0) {
            int e = ment[q];
            int m = sMm[e];
            int cls = (int)sPayT[m][2];
            {
                float p = sigm(cz0[q]);
                float lp = fmaxf(__logf(p), -100.f);
                float lq = fmaxf(__logf(1.f - p), -100.f);
                float t = (lane == cls) ? 1.f : 0.f;
                a_cls += -(t * lp + (1.f - t) * lq);
                float ee = p - t; a_l2 += ee * ee;
            }
            {
                float p = sigm(cz1[q]);
                float lp = fmaxf(__logf(p), -100.f);
                float lq = fmaxf(__logf(1.f - p), -100.f);
                float t = (lane + 32 == cls) ? 1.f : 0.f;
                a_cls += -(t * lp + (1.f - t) * lq);
                float ee = p - t; a_l2 += ee * ee;
            }
            if (lane < 16) {
                float p = sigm(cz2[q]);
                float lp = fmaxf(__logf(p), -100.f);
                float lq = fmaxf(__logf(1.f - p), -100.f);
                float t = (lane + 64 == cls) ? 1.f : 0.f;
                a_cls += -(t * lp + (1.f - t) * lq);
                float ee = p - t; a_l2 += ee * ee;
            }
            if (lane == 0) {
                // txf = tyf = 0 exactly
                float tw = sPayT[m][0], th = sPayT[m][1];
                float ta = sTb[m];
                float msx = sigm(mx0[q]), msy = sigm(my0[q]), mso = sigm(mzo[q]);
                float twt = __logf(__fmaf_rn(tw, c_iaw[anc], 1e-16f));
                float tht = __logf(__fmaf_rn(th, c_iah[anc], 1e-16f));
                float w2 = 2.0f - ta * (1.0f / 361.0f);
                float lqx = fmaxf(__logf(1.f - msx), -100.f);
                float lqy = fmaxf(__logf(1.f - msy), -100.f);
                a_xy += -w2 * (lqx + lqy);
                float dw = mzw[q] - twt, dh = mzh[q] - tht;
                float whs = w2 * (dw * dw + dh * dh);
                a_wh += 0.5f * whs;
                a_obj += -fmaxf(__logf(mso), -100.f);
                float eo2 = mso - 1.f;
                a_l2 += msx * msx + msy * msy + whs + eo2 * eo2;
            }
        }
    }

    // ---- leftover matched entries (n > 24), rare ----
    for (int e = 2 * NWRP + wid; e < n; e += NWRP) {
        int m = sMm[e];
        int idx = sMloc[e];
        int cls = (int)sPayT[m][2];
        size_t cb = base + idx;
        #pragma unroll
        for (int r2 = 0; r2 < 3; r2++) {
            int cc = lane + r2 * 32;
            if (cc < NCc) {
                float z = __ldg(&out[cb + (size_t)(5 + cc) * CELLS]);
                float p = sigm(z);
                float lp = fmaxf(__logf(p), -100.f);
                float lq = fmaxf(__logf(1.f - p), -100.f);
                float t = (cc == cls) ? 1.f : 0.f;
                a_cls += -(t * lp + (1.f - t) * lq);
                float ee = p - t; a_l2 += ee * ee;
            }
        }
        if (lane == 0) {
            float tw = sPayT[m][0], th = sPayT[m][1];
            float ta = sTb[m];
            float msx = sigm(__ldg(&out[cb]));
            float msy = sigm(__ldg(&out[cb + CELLS]));
            float lzw = __ldg(&out[cb + 2 * CELLS]);
            float lzh = __ldg(&out[cb + 3 * CELLS]);
            float mso = sigm(__ldg(&out[cb + 4 * CELLS]));
            float twt = __logf(__fmaf_rn(tw, c_iaw[anc], 1e-16f));
            float tht = __logf(__fmaf_rn(th, c_iah[anc], 1e-16f));
            float w2 = 2.0f - ta * (1.0f / 361.0f);
            float lqx = fmaxf(__logf(1.f - msx), -100.f);
            float lqy = fmaxf(__logf(1.f - msy), -100.f);
            a_xy += -w2 * (lqx + lqy);
            float dw = lzw - twt, dh = lzh - tht;
            float whs = w2 * (dw * dw + dh * dh);
            a_wh += 0.5f * whs;
            a_obj += -fmaxf(__logf(mso), -100.f);
            float eo2 = mso - 1.f;
            a_l2 += msx * msx + msy * msy + whs + eo2 * eo2;
        }
    }

    // ---- reduce ----
    unsigned msk = 0xffffffffu;
    for (int off = 16; off > 0; off >>= 1) {
        a_xy  += __shfl_down_sync(msk, a_xy, off);
        a_wh  += __shfl_down_sync(msk, a_wh, off);
        a_obj += __shfl_down_sync(msk, a_obj, off);
        a_cls += __shfl_down_sync(msk, a_cls, off);
        a_l2  += __shfl_down_sync(msk, a_l2, off);
    }
    if (lane == 0) {
        sRed[wid][0] = a_xy; sRed[wid][1] = a_wh; sRed[wid][2] = a_obj;
        sRed[wid][3] = a_cls; sRed[wid][4] = a_l2;
    }
    __syncthreads();
    if (tid == 0) {
        float r0 = 0.f, r1 = 0.f, r2 = 0.f, r3 = 0.f, r4 = 0.f;
        #pragma unroll
        for (int w = 0; w < NWRP; w++) {
            r0 += sRed[w][0]; r1 += sRed[w][1]; r2 += sRed[w][2];
            r3 += sRed[w][3]; r4 += sRed[w][4];
        }
        atomicAdd(&g_acc[1], (double)r0);
        atomicAdd(&g_acc[2], (double)r1);
        atomicAdd(&g_acc[3], (double)r2);
        atomicAdd(&g_acc[4], (double)r3);
        atomicAdd(&g_acc[5], (double)r4);
        __threadfence();
        int d = atomicAdd(&g_done, 1);
        if (d == NBLK - 1) {
            double xy = atomicAdd(&g_acc[1], 0.0);
            double wh = atomicAdd(&g_acc[2], 0.0);
            double ob = atomicAdd(&g_acc[3], 0.0);
            double cl = atomicAdd(&g_acc[4], 0.0);
            double l2 = atomicAdd(&g_acc[5], 0.0);
            o[0] = (float)(xy + wh + ob + cl);
            o[1] = (float)xy;
            o[2] = (float)wh;
            o[3] = (float)ob;
            o[4] = (float)cl;
            o[5] = (float)l2;
            g_acc[1] = 0.0; g_acc[2] = 0.0; g_acc[3] = 0.0;
            g_acc[4] = 0.0; g_acc[5] = 0.0;
            g_done = 0;
        }
    }
}

extern "C" void kernel_launch(void* const* d_in, const int* in_sizes, int n_in,
                              void* d_out, int out_size) {
    const float* output = (const float*)d_in[0];
    const float* labels = (const float*)d_in[1];
    float* o = (float*)d_out;
    (void)in_sizes; (void)n_in; (void)out_size;

    dim3 grid(BB, 3);
    k_fused<<<grid, NTHR>>>(output, labels, o);
}